// round 1
// baseline (speedup 1.0000x reference)
#include <cuda_runtime.h>
#include <cuda_bf16.h>
#include <cstdint>

// Problem: adaptive_avg_pool2d(x[32,2048,28,28], 7) -> out[32,49,2048]
// H=W=28, pool=7 => exact uniform 4x4 windows (linspace(0,28,8) = 0,4,...,28).
//
// Strategy (HBM-bound, ~218 MB traffic):
//  - Block = (b, 128-channel tile). Warp processes one channel plane at a time,
//    16 planes per warp.
//  - Plane = 784 contiguous f32 = 196 float4. float4 #q covers row h=q/7,
//    horizontal bin j=q%7 exactly -> per-lane partial = (x+y+z+w)/16 for
//    bin (q/28)*7 + q%7.
//  - Accumulate into smem with odd-stride layout acc[c_local*57 + bin]
//    (conflict-light; <=4-way same-address atomic collisions).
//  - Coalesced transposed writeout: out[b, p, c0:c0+128] contiguous.

#define CCH   2048
#define HW    784
#define NQ    196      // float4 per plane
#define TILE_C 128
#define ACC_STRIDE 57  // odd stride: conflict-free transposed readout

__global__ __launch_bounds__(256)
void upp_pool_kernel(const float* __restrict__ x, float* __restrict__ out) {
    __shared__ float acc[TILE_C * ACC_STRIDE];  // 29184 B

    const int b  = blockIdx.y;
    const int c0 = blockIdx.x * TILE_C;
    const int tid  = threadIdx.x;
    const int warp = tid >> 5;
    const int lane = tid & 31;

    // Zero the accumulator tile
    #pragma unroll
    for (int i = tid; i < TILE_C * ACC_STRIDE; i += 256)
        acc[i] = 0.0f;
    __syncthreads();

    // Each warp handles 16 consecutive channels of this tile
    #pragma unroll 2
    for (int cw = 0; cw < 16; ++cw) {
        const int c_local = warp * 16 + cw;
        const size_t plane_off = ((size_t)(b * CCH + c0 + c_local)) * HW;
        const float4* __restrict__ plane =
            reinterpret_cast<const float4*>(x + plane_off);

        #pragma unroll
        for (int k = 0; k < 7; ++k) {
            const int q = lane + 32 * k;
            if (q < NQ) {
                const float4 v = plane[q];                 // coalesced LDG.128
                const float s = (v.x + v.y + v.z + v.w) * 0.0625f;
                const int bin = (q / 28) * 7 + (q % 7);    // i*7 + j
                atomicAdd(&acc[c_local * ACC_STRIDE + bin], s);
            }
        }
    }
    __syncthreads();

    // out[b, p, c] = acc[c*57 + p]; contiguous in c -> coalesced stores
    float* __restrict__ ob = out + (size_t)b * 49 * CCH + c0;
    #pragma unroll
    for (int i = tid; i < 49 * TILE_C; i += 256) {
        const int p = i >> 7;       // 0..48
        const int c = i & (TILE_C - 1);
        ob[p * CCH + c] = acc[c * ACC_STRIDE + p];
    }
}

extern "C" void kernel_launch(void* const* d_in, const int* in_sizes, int n_in,
                              void* d_out, int out_size) {
    const float* x = (const float*)d_in[0];
    float* out = (float*)d_out;
    dim3 grid(CCH / TILE_C, 32);   // (16, 32) = 512 blocks
    upp_pool_kernel<<<grid, 256>>>(x, out);
}

// round 2
// speedup vs baseline: 1.2228x; 1.2228x over previous
#include <cuda_runtime.h>
#include <cuda_bf16.h>
#include <cstdint>

// adaptive_avg_pool2d(x[32,2048,28,28], 7) -> out[32,49,2048]
// linspace(0,28,8) = 0,4,...,28 => exact uniform 4x4 windows.
//
// R2: latency-bound fix. Grid 512 -> 2048 blocks (TILE_C 128 -> 32) so each SM
// holds ~14 blocks; smem 29KB -> 7.3KB; warp handles 4 channels with loads
// batched across channels for MLP.

#define CCH    2048
#define HW     784
#define NQ     196      // float4 per 28x28 plane
#define TILE_C 32
#define ACC_STRIDE 57   // odd stride: conflict-free transposed readout

__global__ __launch_bounds__(256, 6)
void upp_pool_kernel(const float* __restrict__ x, float* __restrict__ out) {
    __shared__ float acc[TILE_C * ACC_STRIDE];  // 7296 B

    const int b    = blockIdx.y;
    const int c0   = blockIdx.x * TILE_C;
    const int tid  = threadIdx.x;
    const int warp = tid >> 5;
    const int lane = tid & 31;

    #pragma unroll
    for (int i = tid; i < TILE_C * ACC_STRIDE; i += 256)
        acc[i] = 0.0f;
    __syncthreads();

    // Each warp owns 4 consecutive channels of this 32-channel tile.
    // Unroll channel pairs so loads from 2 planes are in flight together.
    #pragma unroll 2
    for (int cw = 0; cw < 4; ++cw) {
        const int c_local = warp * 4 + cw;
        const size_t plane_off = ((size_t)(b * CCH + c0 + c_local)) * HW;
        const float4* __restrict__ plane =
            reinterpret_cast<const float4*>(x + plane_off);

        #pragma unroll
        for (int k = 0; k < 7; ++k) {
            const int q = lane + 32 * k;
            if (q < NQ) {
                const float4 v = plane[q];                 // coalesced LDG.128
                const float s = (v.x + v.y + v.z + v.w) * 0.0625f;
                const int bin = (q / 28) * 7 + (q % 7);    // i*7 + j
                atomicAdd(&acc[c_local * ACC_STRIDE + bin], s);
            }
        }
    }
    __syncthreads();

    // out[b, p, c0+c] = acc[c*57 + p]; contiguous in c -> coalesced.
    // smem read banks: (57c + p) % 32 = (25c + p) % 32, permutation in c.
    float* __restrict__ ob = out + (size_t)b * 49 * CCH + c0;
    #pragma unroll
    for (int i = tid; i < 49 * TILE_C; i += 256) {
        const int p = i >> 5;              // 0..48
        const int c = i & (TILE_C - 1);    // 0..31
        ob[p * CCH + c] = acc[c * ACC_STRIDE + p];
    }
}

extern "C" void kernel_launch(void* const* d_in, const int* in_sizes, int n_in,
                              void* d_out, int out_size) {
    const float* x = (const float*)d_in[0];
    float* out = (float*)d_out;
    dim3 grid(CCH / TILE_C, 32);   // (64, 32) = 2048 blocks
    upp_pool_kernel<<<grid, 256>>>(x, out);
}

// round 3
// speedup vs baseline: 2.0689x; 1.6919x over previous
#include <cuda_runtime.h>
#include <cuda_bf16.h>
#include <cstdint>

// adaptive_avg_pool2d(x[32,2048,28,28], 7) -> out[32,49,2048]
// linspace(0,28,8) = 0,4,...,28 => exact uniform 4x4 windows.
//
// R3: kill the smem atomics (ATOMS was ~450 cyc MIO per warp-channel).
// Phase 1: coalesced LDG.128, per-lane horizontal partial -> plain STS into
//          per-warp stage[196] (conflict-free).
// Phase 2: warp-local bin reduce: bin(i,j) = sum of stage[28i+7r+j], r=0..3.
//          Unique writer per (c,bin) -> plain store into transpose buffer.
// launch_bounds(256,8) -> regs<=32 -> 64 warps/SM.

#define CCH    2048
#define HW     784
#define NQ     196       // float4 per 28x28 plane
#define TILE_C 32
#define ACC_STRIDE 57    // odd stride: conflict-free transposed readout
#define STG_STRIDE 200   // per-warp stage stride

__global__ __launch_bounds__(256, 8)
void upp_pool_kernel(const float* __restrict__ x, float* __restrict__ out) {
    __shared__ float stage[8 * STG_STRIDE];     // 6400 B
    __shared__ float acc[TILE_C * ACC_STRIDE];  // 7296 B

    const int b    = blockIdx.y;
    const int c0   = blockIdx.x * TILE_C;
    const int tid  = threadIdx.x;
    const int warp = tid >> 5;
    const int lane = tid & 31;
    const int wbase = warp * STG_STRIDE;

    // Per-lane bin offsets, hoisted out of the channel loop.
    // bin b0 = lane (0..31); bin b1 = lane+32 (valid if < 49, i.e. lane < 17)
    const int b0 = lane;
    const int o0 = 28 * (b0 / 7) + (b0 % 7);
    const int b1 = lane + 32;
    const int o1 = 28 * (b1 / 7) + (b1 % 7);

    // Each warp owns 4 consecutive channels of this 32-channel tile.
    #pragma unroll
    for (int cw = 0; cw < 4; ++cw) {
        const int c_local = warp * 4 + cw;
        const size_t plane_off = ((size_t)(b * CCH + c0 + c_local)) * HW;
        const float4* __restrict__ plane =
            reinterpret_cast<const float4*>(x + plane_off);

        // Phase 1: coalesced loads -> horizontal partials -> stage (plain STS)
        #pragma unroll
        for (int k = 0; k < 7; ++k) {
            const int q = lane + 32 * k;
            if (q < NQ) {
                const float4 v = plane[q];   // LDG.128, fully coalesced
                stage[wbase + q] = (v.x + v.y + v.z + v.w) * 0.0625f;
            }
        }
        __syncwarp();

        // Phase 2: vertical reduce over 4 rows per bin (warp-local, no atomics)
        {
            const float r0 = stage[wbase + o0]      + stage[wbase + o0 + 7] +
                             stage[wbase + o0 + 14] + stage[wbase + o0 + 21];
            acc[c_local * ACC_STRIDE + b0] = r0;
        }
        if (lane < 17) {
            const float r1 = stage[wbase + o1]      + stage[wbase + o1 + 7] +
                             stage[wbase + o1 + 14] + stage[wbase + o1 + 21];
            acc[c_local * ACC_STRIDE + b1] = r1;
        }
        __syncwarp();   // WAR: stage reused by next channel
    }
    __syncthreads();

    // out[b, p, c0+c] = acc[c*57 + p]; contiguous in c -> coalesced stores
    float* __restrict__ ob = out + (size_t)b * 49 * CCH + c0;
    #pragma unroll
    for (int i = tid; i < 49 * TILE_C; i += 256) {
        const int p = i >> 5;              // 0..48
        const int c = i & (TILE_C - 1);    // 0..31
        ob[p * CCH + c] = acc[c * ACC_STRIDE + p];
    }
}

extern "C" void kernel_launch(void* const* d_in, const int* in_sizes, int n_in,
                              void* d_out, int out_size) {
    const float* x = (const float*)d_in[0];
    float* out = (float*)d_out;
    dim3 grid(CCH / TILE_C, 32);   // (64, 32) = 2048 blocks
    upp_pool_kernel<<<grid, 256>>>(x, out);
}